// round 17
// baseline (speedup 1.0000x reference)
#include <cuda_runtime.h>
#include <cuda_bf16.h>
#include <cstdint>

#define BATCH   4096
#define D       128
#define NP      16
#define HID     256
#define XSTRIDE 144           // D + NPARAMS
#define NTOT    (BATCH * D)   // 524288 = 2^19
#define NMASK   (NTOT - 1)
#define NSTEPS  8             // validated R9/R13/R15: rel_err ~1.44e-4 at N=8

typedef unsigned long long u64;
typedef unsigned int       u32;

// ---------------- packed f32x2 helpers (used by ODE only) ----------------
__device__ __forceinline__ u64 pk(float lo, float hi) {
    u64 r; asm("mov.b64 %0, {%1, %2};" : "=l"(r) : "f"(lo), "f"(hi)); return r;
}
__device__ __forceinline__ void upk(float& lo, float& hi, u64 v) {
    asm("mov.b64 {%0, %1}, %2;" : "=f"(lo), "=f"(hi) : "l"(v));
}
__device__ __forceinline__ u64 fma2(u64 a, u64 b, u64 c) {
    u64 r; asm("fma.rn.f32x2 %0, %1, %2, %3;" : "=l"(r) : "l"(a), "l"(b), "l"(c)); return r;
}
__device__ __forceinline__ u64 mul2(u64 a, u64 b) {
    u64 r; asm("mul.rn.f32x2 %0, %1, %2;" : "=l"(r) : "l"(a), "l"(b)); return r;
}
__device__ __forceinline__ u64 add2(u64 a, u64 b) {
    u64 r; asm("add.rn.f32x2 %0, %1, %2;" : "=l"(r) : "l"(a), "l"(b)); return r;
}

// ---------------- cp.async helpers ----------------
__device__ __forceinline__ u32 smem_u32(const void* p) {
    return (u32)__cvta_generic_to_shared(p);
}
__device__ __forceinline__ void cp16(void* dst, const void* src) {
    asm volatile("cp.async.cg.shared.global [%0], [%1], 16;\n"
                 :: "r"(smem_u32(dst)), "l"(src));
}
__device__ __forceinline__ void cp_commit() {
    asm volatile("cp.async.commit_group;\n");
}
template<int N> __device__ __forceinline__ void cp_wait() {
    asm volatile("cp.async.wait_group %0;\n" :: "n"(N));
}

// ---------------- mma.sync bf16 + ldmatrix ----------------
__device__ __forceinline__ void mma_bf16(float* d, const u32* a, const u32* b) {
    asm volatile(
        "mma.sync.aligned.m16n8k16.row.col.f32.bf16.bf16.f32 "
        "{%0,%1,%2,%3}, {%4,%5,%6,%7}, {%8,%9}, {%0,%1,%2,%3};"
        : "+f"(d[0]), "+f"(d[1]), "+f"(d[2]), "+f"(d[3])
        : "r"(a[0]), "r"(a[1]), "r"(a[2]), "r"(a[3]), "r"(b[0]), "r"(b[1]));
}
__device__ __forceinline__ void ldsm4(u32& r0, u32& r1, u32& r2, u32& r3, u32 addr) {
    asm volatile("ldmatrix.sync.aligned.m8n8.x4.shared.b16 {%0,%1,%2,%3}, [%4];"
                 : "=r"(r0), "=r"(r1), "=r"(r2), "=r"(r3) : "r"(addr));
}

// ---------------- global scratch (allocation-free contract) ----------------
__device__ __align__(16) __nv_bfloat16 g_Whi[3][HID * HID];
__device__ __align__(16) __nv_bfloat16 g_Wlo[3][HID * HID];
__device__ __align__(16) float g_w2[NTOT];   // omega0^2 [row][128]
__device__ __align__(16) float g_c [NTOT];   // coupling [row][128]

// ============================================================================
// weight prep: f32 -> bf16 hi/lo for the three 256x256 layers.
// ============================================================================
__global__ void __launch_bounds__(256) prep_w_kernel(
    const float* __restrict__ w0, const float* __restrict__ w1,
    const float* __restrict__ w_out)
{
    const float* Ws[3] = { w0, w1, w_out };
    const int t = blockIdx.x * 256 + threadIdx.x;   // 0..16383
    #pragma unroll 1
    for (int i = 0; i < 12; i++) {
        int e = t + i * 16384;               // < 196608 = 3*65536
        int L = e >> 16;
        int rem = e & 65535;
        float wv = Ws[L][rem];
        __nv_bfloat16 hi = __float2bfloat16(wv);
        g_Whi[L][rem] = hi;
        g_Wlo[L][rem] = __float2bfloat16(wv - __bfloat162float(hi));
    }
}

// ============================================================================
// FUSED MLP kernel: input layer + 3x(256x256) layers per 32-row block.
// Grid 128, 256 threads (8 warps, 2x4: warp tile 16 rows x 64 cols).
// Activations live in smem (hi/lo planes, 4 chunks of 64 cols, 144B rows),
// ping-ponged A0<->A1. Weights staged per 64-col k-chunk, depth-1 cp.async
// double-buffer W0<->W1 (R6 pattern: wait<0>; SYNC; stage(next); compute).
// Layer-2 epilogue writes omega^2 / coupling straight to g_w2 / g_c.
// smem map (bytes):
//   A0_hi 0      A0_lo 18432   A1_hi 36864   A1_lo 55296
//   W0_hi 73728  W0_lo 110592  W1_hi 147456  W1_lo 184320   total 221184
// Init overlays: Wc (w_in, stride-17 floats) in W1 region; P in A1 region.
// ============================================================================
#define A_BUF   36864
#define A_LOPL  18432
#define W_BASE  73728
#define W_BUF   73728
#define W_LOPL  36864
#define MLP_SMEM 221184

__global__ void __launch_bounds__(256) fused_mlp_kernel(
    const float* __restrict__ x,
    const float* __restrict__ w_in, const float* __restrict__ b_in,
    const float* __restrict__ b0,   const float* __restrict__ b1,
    const float* __restrict__ b_out)
{
    extern __shared__ char sm[];
    const int tid  = threadIdx.x;
    const int wid  = tid >> 5;
    const int lane = tid & 31;
    const int gid  = lane >> 2;
    const int t4   = lane & 3;
    const int wm   = wid >> 2;        // 0..1 (16 rows each)
    const int wn   = wid & 3;         // 0..3 (64 cols each)
    const int row0 = blockIdx.x * 32;

    float* Wc = (float*)(sm + W_BASE + W_BUF);   // w_in staging (17408 floats)
    float* P  = (float*)(sm + A_BUF);            // params 32x16

    // ---- init staging: params, w_in, and prefetch layer-0 chunk-0 ----
    for (int idx = tid; idx < 32 * NP; idx += 256) {
        int r = idx >> 4, k = idx & 15;
        P[idx] = x[(row0 + r) * XSTRIDE + D + k];
    }
    for (int idx = tid; idx < HID * NP; idx += 256) {
        int j = idx >> 4, k = idx & 15;
        Wc[j * 17 + k] = w_in[idx];
    }
    {   // stage W layer0 chunk0 into W0 (hi+lo), 256 rows x 8 granules each
        for (int i = tid; i < HID * 8; i += 256) {
            int row = i >> 3, g = i & 7;
            cp16(sm + W_BASE + row * 144 + g * 16,
                 g_Whi[0] + (size_t)row * HID + g * 8);
            cp16(sm + W_BASE + W_LOPL + row * 144 + g * 16,
                 g_Wlo[0] + (size_t)row * HID + g * 8);
        }
        cp_commit();
    }
    __syncthreads();

    // ---- input layer: 16 -> 256, relu, bf16 hi/lo split into A0 ----
    {
        const int j = tid;
        float w[16];
        #pragma unroll
        for (int k = 0; k < 16; k++) w[k] = Wc[j * 17 + k];
        const float b = b_in[j];
        char* hiP = sm + (j >> 6) * 4608 + (j & 63) * 2;
        #pragma unroll 1
        for (int r = 0; r < 32; r++) {
            float acc = b;
            #pragma unroll
            for (int k = 0; k < 16; k++) acc = fmaf(P[r * 16 + k], w[k], acc);
            float h = fmaxf(acc, 0.0f);
            __nv_bfloat16 hi = __float2bfloat16(h);
            __nv_bfloat16 lo = __float2bfloat16(h - __bfloat162float(hi));
            *(__nv_bfloat16*)(hiP + r * 144)          = hi;
            *(__nv_bfloat16*)(hiP + A_LOPL + r * 144) = lo;
        }
    }

    // ---- ldmatrix lane offsets (within a plane) ----
    const int l8 = lane & 7, lt = lane >> 3;
    const u32 sb = smem_u32(sm);
    const u32 aOff = (u32)((wm * 16 + (lt & 1) * 8 + l8) * 144 + ((lt >> 1) * 8) * 2);
    const u32 bOff = (u32)((wn * 64 + (lt >> 1) * 8 + l8) * 144 + ((lt & 1) * 8) * 2);

    const float* Bs[3] = { b0, b1, b_out };

    #pragma unroll 1
    for (int layer = 0; layer < 3; ++layer) {
        const int cur  = layer & 1;            // A read buffer
        const int nxt  = cur ^ 1;
        const u32 aBase = sb + (u32)cur * A_BUF;

        float acc[8][4];
        #pragma unroll
        for (int nt = 0; nt < 8; nt++)
            #pragma unroll
            for (int e = 0; e < 4; e++) acc[nt][e] = 0.0f;

        #pragma unroll 1
        for (int ch = 0; ch < 4; ch++) {
            const int q = layer * 4 + ch;
            const u32 wBase = sb + W_BASE + (u32)(q & 1) * W_BUF;

            cp_wait<0>();      // chunk q staged (committed last iteration)
            __syncthreads();   // visible to all; also orders A hand-offs and
                               // frees the other W buffer for restaging
            if (q < 11) {      // stage chunk q+1 (next ch, or next layer ch0)
                const int nl = (ch < 3) ? layer : layer + 1;
                const int kc = (ch < 3) ? (ch + 1) * 64 : 0;
                char* wd = sm + W_BASE + ((q + 1) & 1) * W_BUF;
                for (int i = tid; i < HID * 8; i += 256) {
                    int row = i >> 3, g = i & 7;
                    cp16(wd + row * 144 + g * 16,
                         g_Whi[nl] + (size_t)row * HID + kc + g * 8);
                    cp16(wd + W_LOPL + row * 144 + g * 16,
                         g_Wlo[nl] + (size_t)row * HID + kc + g * 8);
                }
                cp_commit();
            }

            const u32 aC = aBase + (u32)ch * 4608;
            #pragma unroll
            for (int ks = 0; ks < 4; ks++) {
                const u32 kb = (u32)ks * 32;
                u32 aH[4], aL[4], bH[16], bL[16];
                {
                    u32 ad = aC + aOff + kb;
                    ldsm4(aH[0], aH[1], aH[2], aH[3], ad);
                    ldsm4(aL[0], aL[1], aL[2], aL[3], ad + A_LOPL);
                }
                #pragma unroll
                for (int p = 0; p < 4; p++) {   // ntile pairs
                    u32 bd = wBase + bOff + (u32)(p * 2304) + kb;  // 16*144
                    ldsm4(bH[4 * p], bH[4 * p + 1], bH[4 * p + 2], bH[4 * p + 3], bd);
                    ldsm4(bL[4 * p], bL[4 * p + 1], bL[4 * p + 2], bL[4 * p + 3],
                          bd + W_LOPL);
                }
                #pragma unroll
                for (int nt = 0; nt < 8; nt++) {
                    mma_bf16(acc[nt], aH, bH + 2 * nt);   // hi*hi
                    mma_bf16(acc[nt], aH, bL + 2 * nt);   // hi*lo
                    mma_bf16(acc[nt], aL, bH + 2 * nt);   // lo*hi
                }
            }
        }

        // ---- epilogue ----
        const float* bias = Bs[layer];
        if (layer < 2) {
            char* hiN = sm + nxt * A_BUF;
            #pragma unroll
            for (int nt = 0; nt < 8; nt++) {
                const int n = wn * 64 + nt * 8 + 2 * t4;
                const float b0v = bias[n];
                const float b1v = bias[n + 1];
                #pragma unroll
                for (int rr = 0; rr < 2; rr++) {
                    const int ml = wm * 16 + gid + rr * 8;   // local row
                    float v0 = fmaxf(acc[nt][2 * rr]     + b0v, 0.0f);
                    float v1 = fmaxf(acc[nt][2 * rr + 1] + b1v, 0.0f);
                    __nv_bfloat16 h0 = __float2bfloat16(v0);
                    __nv_bfloat16 h1 = __float2bfloat16(v1);
                    __nv_bfloat162 hh; hh.x = h0; hh.y = h1;
                    __nv_bfloat162 ll;
                    ll.x = __float2bfloat16(v0 - __bfloat162float(h0));
                    ll.y = __float2bfloat16(v1 - __bfloat162float(h1));
                    char* pdst = hiN + (n >> 6) * 4608 + ml * 144 + (n & 63) * 2;
                    *(u32*)(pdst)          = *(u32*)&hh;
                    *(u32*)(pdst + A_LOPL) = *(u32*)&ll;
                }
            }
        } else {
            #pragma unroll
            for (int nt = 0; nt < 8; nt++) {
                const int n = wn * 64 + nt * 8 + 2 * t4;
                const float b0v = bias[n];
                const float b1v = bias[n + 1];
                #pragma unroll
                for (int rr = 0; rr < 2; rr++) {
                    const int m = row0 + wm * 16 + gid + rr * 8;
                    float c0 = acc[nt][2 * rr]     + b0v;
                    float c1 = acc[nt][2 * rr + 1] + b1v;
                    if (n < 128) {
                        float o0 = fmaf(c0, 1.5f, 0.5f);
                        float o1 = fmaf(c1, 1.5f, 0.5f);
                        *(float2*)(g_w2 + (size_t)m * D + n) =
                            make_float2(o0 * o0, o1 * o1);
                    } else {
                        *(float2*)(g_c + (size_t)m * D + (n - 128)) =
                            make_float2(c0, c1);
                    }
                }
            }
        }
    }
}

// ============================================================================
// ODE: one warp per batch row (128-ring), 4 elems/thread, RKN4 (3 evals/step).
// ============================================================================
__device__ __forceinline__ void accel2(const u64 Y[2], const u64 NW[2],
                                       const u64 C[2],  const u64 CR[2],
                                       const u64 NS[2], int lane, u64 A[2])
{
    float y0, y1, y2, y3;
    upk(y0, y1, Y[0]); upk(y2, y3, Y[1]);
    float yl = __shfl_sync(0xffffffffu, y3, (lane + 31) & 31);
    float yr = __shfl_sync(0xffffffffu, y0, (lane + 1) & 31);
    u64 L0 = pk(yl, y0);
    u64 M  = pk(y1, y2);
    u64 R1 = pk(y3, yr);
    u64 S0 = pk(__sinf(y0), __sinf(y1));
    u64 S1 = pk(__sinf(y2), __sinf(y3));
    u64 a0 = mul2(CR[0], L0);
    a0 = fma2(C[0],  M,    a0);
    a0 = fma2(NS[0], Y[0], a0);
    a0 = fma2(NW[0], S0,   a0);
    u64 a1 = mul2(CR[1], M);
    a1 = fma2(C[1],  R1,   a1);
    a1 = fma2(NS[1], Y[1], a1);
    a1 = fma2(NW[1], S1,   a1);
    A[0] = a0; A[1] = a1;
}

__global__ void __launch_bounds__(128) ode_kernel(const float* __restrict__ x,
                                                  float* __restrict__ out)
{
    const int gtid = blockIdx.x * 128 + threadIdx.x;
    const int b    = gtid >> 5;
    const int lane = threadIdx.x & 31;
    const int base = b * D + lane * 4;

    const float TWO_PI = 6.2831853071795864f;
    const float PI_F   = 3.1415926535897932f;

    u64 Y[2], V[2], NW[2], Cc[2], CR[2], NS[2];
    {
        float4 xin = *reinterpret_cast<const float4*>(x + b * XSTRIDE + lane * 4);
        Y[0] = pk(fmaf(xin.x, TWO_PI, -PI_F), fmaf(xin.y, TWO_PI, -PI_F));
        Y[1] = pk(fmaf(xin.z, TWO_PI, -PI_F), fmaf(xin.w, TWO_PI, -PI_F));
        V[0] = 0ull; V[1] = 0ull;

        float4 wv = *reinterpret_cast<const float4*>(g_w2 + base);
        NW[0] = pk(-wv.x, -wv.y);
        NW[1] = pk(-wv.z, -wv.w);
        float4 cv = *reinterpret_cast<const float4*>(g_c + base);
        Cc[0] = pk(cv.x, cv.y);
        Cc[1] = pk(cv.z, cv.w);
        float crl = g_c[(base - 1) & NMASK];   // flat roll crosses rows
        CR[0] = pk(crl,  cv.x);
        CR[1] = pk(cv.y, cv.z);
        NS[0] = pk(-(cv.x + crl),  -(cv.y + cv.x));
        NS[1] = pk(-(cv.z + cv.y), -(cv.w + cv.z));
    }

    const float TEND = 59.0f / 30.0f;
    const float H    = TEND / (float)NSTEPS;
    const u64 PH2  = pk(0.5f * H,              0.5f * H);
    const u64 PHH8 = pk(H * H * 0.125f,        H * H * 0.125f);
    const u64 PH   = pk(H,                     H);
    const u64 PHH2 = pk(H * H * 0.5f,          H * H * 0.5f);
    const u64 PHH6 = pk(H * H * (1.0f/6.0f),   H * H * (1.0f/6.0f));
    const u64 PH6  = pk(H * (1.0f/6.0f),       H * (1.0f/6.0f));
    const u64 P2   = pk(2.0f, 2.0f);
    const u64 P4   = pk(4.0f, 4.0f);

    #pragma unroll 1
    for (int stp = 0; stp < NSTEPS; ++stp) {
        u64 K1[2], K2[2], K3[2], Y2[2], Y3[2], T[2];
        accel2(Y, NW, Cc, CR, NS, lane, K1);
        #pragma unroll
        for (int i = 0; i < 2; i++)
            Y2[i] = fma2(PHH8, K1[i], fma2(PH2, V[i], Y[i]));
        accel2(Y2, NW, Cc, CR, NS, lane, K2);
        #pragma unroll
        for (int i = 0; i < 2; i++) {
            T[i]  = fma2(PH, V[i], Y[i]);
            Y3[i] = fma2(PHH2, K2[i], T[i]);
        }
        accel2(Y3, NW, Cc, CR, NS, lane, K3);
        #pragma unroll
        for (int i = 0; i < 2; i++) {
            Y[i] = fma2(PHH6, fma2(P2, K2[i], K1[i]), T[i]);
            V[i] = fma2(PH6, add2(fma2(P4, K2[i], K1[i]), K3[i]), V[i]);
        }
    }

    float o0, o1, o2, o3;
    upk(o0, o1, Y[0]); upk(o2, o3, Y[1]);
    float4 o;
    o.x = o0 * 0.4f;   // /A_NORM (=2.5), B_NORM=0
    o.y = o1 * 0.4f;
    o.z = o2 * 0.4f;
    o.w = o3 * 0.4f;
    *reinterpret_cast<float4*>(out + base) = o;
}

// ============================================================================
extern "C" void kernel_launch(void* const* d_in, const int* in_sizes, int n_in,
                              void* d_out, int out_size)
{
    const float* x     = (const float*)d_in[0];
    const float* w_in  = (const float*)d_in[1];
    const float* b_in  = (const float*)d_in[2];
    const float* w0    = (const float*)d_in[3];
    const float* b0    = (const float*)d_in[4];
    const float* w1    = (const float*)d_in[5];
    const float* b1    = (const float*)d_in[6];
    const float* w_out = (const float*)d_in[7];
    const float* b_out = (const float*)d_in[8];

    cudaFuncSetAttribute(fused_mlp_kernel,
                         cudaFuncAttributeMaxDynamicSharedMemorySize, MLP_SMEM);

    prep_w_kernel<<<64, 256>>>(w0, w1, w_out);
    fused_mlp_kernel<<<128, 256, MLP_SMEM>>>(x, w_in, b_in, b0, b1, b_out);
    ode_kernel<<<(BATCH * 32) / 128, 128>>>(x, (float*)d_out);
}